// round 7
// baseline (speedup 1.0000x reference)
#include <cuda_runtime.h>
#include <cuda_fp16.h>
#include <cstdint>
#include <cstddef>

// ---------------------------------------------------------------------------
// QLinearLayer: mixed 4/6/8-bit microscaled GEMM, M=8192 N=4096 K=4096, G=32.
// Plain sm_100 (no 'a' features) -> mma.sync + ldmatrix + cp.async.
// Pass 1: TWO fused dequant kernels (A rows, B rows) -> fp16 scratch.
// Pass 2: pipelined fp16 HMMA GEMM, CTA 256x128, warp 64x64, 5 stages.
// Exactly 3 launches per call so ncu (-s 5 -c 1) profiles the GEMM.
// ---------------------------------------------------------------------------

static __device__ __half g_Adeq[(size_t)8192 * 4096];  // 64 MB
static __device__ __half g_Bdeq[(size_t)4096 * 4096];  // 32 MB

#define DI static __device__ __forceinline__

DI uint32_t smem_u32(const void* p) {
    uint32_t a;
    asm("{ .reg .u64 t; cvta.to.shared.u64 t, %1; cvt.u32.u64 %0, t; }"
        : "=r"(a) : "l"(p));
    return a;
}
DI void cp_async16(uint32_t smem, const void* gmem) {
    asm volatile("cp.async.cg.shared.global [%0], [%1], 16;"
                 :: "r"(smem), "l"(gmem) : "memory");
}
DI void cp_commit() { asm volatile("cp.async.commit_group;" ::: "memory"); }
template <int N> DI void cp_wait() {
    asm volatile("cp.async.wait_group %0;" :: "n"(N) : "memory");
}
DI void ldsm4(uint32_t* r, uint32_t addr) {
    asm volatile("ldmatrix.sync.aligned.m8n8.x4.shared.b16 {%0,%1,%2,%3}, [%4];"
                 : "=r"(r[0]), "=r"(r[1]), "=r"(r[2]), "=r"(r[3]) : "r"(addr));
}
// b0 = k-half 0 of one n8 group, b1 = k-half 1 of the SAME n8 group.
DI void mma16816(float* d, const uint32_t* a, uint32_t b0, uint32_t b1) {
    asm volatile(
        "mma.sync.aligned.m16n8k16.row.col.f32.f16.f16.f32 "
        "{%0,%1,%2,%3}, {%4,%5,%6,%7}, {%8,%9}, {%0,%1,%2,%3};"
        : "+f"(d[0]), "+f"(d[1]), "+f"(d[2]), "+f"(d[3])
        : "r"(a[0]), "r"(a[1]), "r"(a[2]), "r"(a[3]), "r"(b0), "r"(b1));
}

// ---------------------------------------------------------------------------
// Fused dequant: one block per row covers all three K segments.
// block = 512 threads, thread t handles global cols [8t, 8t+8).
//   seg layout: int4 [0,2048) / int6 [2048,3072) / int8 [3072,4096)
// ---------------------------------------------------------------------------
__global__ void __launch_bounds__(512)
dequant_fused_kernel(const int* __restrict__ Q4, const float* __restrict__ SF4,
                     const int* __restrict__ Q6, const float* __restrict__ SF6,
                     const int* __restrict__ Q8, const float* __restrict__ SF8,
                     __half* __restrict__ dst) {
    const int m = blockIdx.x;
    const int c = threadIdx.x * 8;          // global col in [0,4096)

    const int* q;
    float s;
    if (c < 2048) {
        q = Q4 + (size_t)m * 2048 + c;
        s = __ldg(&SF4[(size_t)m * 64 + (c >> 5)]);
    } else if (c < 3072) {
        const int cl = c - 2048;
        q = Q6 + (size_t)m * 1024 + cl;
        s = __ldg(&SF6[(size_t)m * 32 + (cl >> 5)]);
    } else {
        const int cl = c - 3072;
        q = Q8 + (size_t)m * 1024 + cl;
        s = __ldg(&SF8[(size_t)m * 32 + (cl >> 5)]);
    }
    int4 q0 = __ldg((const int4*)q);
    int4 q1 = __ldg((const int4*)q + 1);
    union { uint4 u; __half2 h2[4]; } pk;
    pk.h2[0] = __floats2half2_rn((float)q0.x * s, (float)q0.y * s);
    pk.h2[1] = __floats2half2_rn((float)q0.z * s, (float)q0.w * s);
    pk.h2[2] = __floats2half2_rn((float)q1.x * s, (float)q1.y * s);
    pk.h2[3] = __floats2half2_rn((float)q1.z * s, (float)q1.w * s);
    *(uint4*)(dst + (size_t)m * 4096 + c) = pk.u;
}

// ---------------------------------------------------------------------------
// GEMM configuration
//   CTA tile 256(M) x 128(N), 8 warps as 4(M) x 2(N) -> warp tile 64 x 64.
//   K-chunk = 32 halves (64B per row), 5-stage cp.async pipeline.
//   SMEM rows padded to 80B: 8 consecutive rows at stride 80 hit 8 distinct
//   16B phases -> conflict-free ldmatrix; cp.async writes 4-way balanced.
// ---------------------------------------------------------------------------
static constexpr int STAGES  = 5;
static constexpr int ROWB    = 80;
static constexpr int TILEA   = 256 * ROWB;         // 20480
static constexpr int TILEB   = 128 * ROWB;         // 10240
static constexpr int STAGE_B = TILEA + TILEB;      // 30720
static constexpr int SMEM_SZ = STAGES * STAGE_B;   // 153600
static constexpr int NKCH    = 4096 / 32;          // 128 K chunks

__global__ void __launch_bounds__(256, 1)
mixed_gemm_kernel(const float* __restrict__ bias, float* __restrict__ out) {
    extern __shared__ __align__(128) char smem[];
    const uint32_t sb = smem_u32(smem);
    const int tid  = threadIdx.x;
    const int lane = tid & 31;
    const int w    = tid >> 5;
    const int wm   = w >> 1;       // 0..3  (M quarters of CTA tile)
    const int wn   = w & 1;        // 0..1  (N halves)
    const int mt   = blockIdx.y;   // 32 M tiles (256 rows each)
    const int ntb  = blockIdx.x;   // 32 N tiles (128 rows each)

    const char* gA = (const char*)g_Adeq + (size_t)mt  * 256 * 8192;
    const char* gB = (const char*)g_Bdeq + (size_t)ntb * 128 * 8192;

    // cp.async coords: A has 1024 16B chunks (4/thread), B has 512 (2/thread).
    const int ar[4] = { tid >> 2, (tid + 256) >> 2, (tid + 512) >> 2, (tid + 768) >> 2 };
    const int br[2] = { tid >> 2, (tid + 256) >> 2 };
    const int cc = (tid & 3) * 16;

    auto load_stage = [&](int s, int kc) {
        const uint32_t sA = sb + s * STAGE_B;
        const uint32_t sB = sA + TILEA;
        const size_t  gk = (size_t)kc * 64 + cc;
        #pragma unroll
        for (int i = 0; i < 4; ++i)
            cp_async16(sA + ar[i] * ROWB + cc, gA + (size_t)ar[i] * 8192 + gk);
        #pragma unroll
        for (int i = 0; i < 2; ++i)
            cp_async16(sB + br[i] * ROWB + cc, gB + (size_t)br[i] * 8192 + gk);
    };

    // prologue
    #pragma unroll
    for (int s = 0; s < STAGES - 1; ++s) { load_stage(s, s); cp_commit(); }

    float acc[4][8][4];
    #pragma unroll
    for (int i = 0; i < 4; ++i)
        #pragma unroll
        for (int j = 0; j < 8; ++j)
            #pragma unroll
            for (int k = 0; k < 4; ++k) acc[i][j][k] = 0.f;

    // ldmatrix lane mapping (x4): lanes 0-7 rows r..r+7 @khalf0, 8-15 rows+8,
    // 16-23 rows @khalf1, 24-31 rows+8 @khalf1.
    const int grp   = lane >> 3;
    const int rin16 = (lane & 7) + ((grp & 1) << 3);
    const int kh16  = (grp >> 1) * 16;

    int s = 0;
    for (int kc = 0; kc < NKCH; ++kc) {
        cp_wait<STAGES - 2>();
        __syncthreads();

        const int kl = kc + STAGES - 1;
        if (kl < NKCH) load_stage(kl % STAGES, kl);
        cp_commit();

        const uint32_t stA = sb + s * STAGE_B + (wm * 64 + rin16) * ROWB + kh16;
        const uint32_t stB = sb + s * STAGE_B + TILEA + (wn * 64 + rin16) * ROWB + kh16;

        #pragma unroll
        for (int ks = 0; ks < 2; ++ks) {          // two k16 steps per chunk
            uint32_t af[4][4], bf[4][4];
            #pragma unroll
            for (int i = 0; i < 4; ++i)
                ldsm4(af[i], stA + i * 16 * ROWB + ks * 32);
            #pragma unroll
            for (int j = 0; j < 4; ++j)
                ldsm4(bf[j], stB + j * 16 * ROWB + ks * 32);
            // bf[j]: [0]=(n0-7,k0-7) [1]=(n8-15,k0-7) [2]=(n0-7,k8-15) [3]=(n8-15,k8-15)
            #pragma unroll
            for (int i = 0; i < 4; ++i) {
                #pragma unroll
                for (int j = 0; j < 4; ++j) {
                    mma16816(acc[i][2 * j],     af[i], bf[j][0], bf[j][2]);
                    mma16816(acc[i][2 * j + 1], af[i], bf[j][1], bf[j][3]);
                }
            }
        }
        if (++s == STAGES) s = 0;
    }

    // ------------------------- epilogue -------------------------
    const int quad = lane >> 2;
    const int qt   = lane & 3;
    const int mbase = mt * 256 + wm * 64;
    const int nbase = ntb * 128 + wn * 64;

    #pragma unroll
    for (int j = 0; j < 8; ++j) {
        const int col = nbase + j * 8 + qt * 2;
        const float b0 = __ldg(bias + col);
        const float b1 = __ldg(bias + col + 1);
        #pragma unroll
        for (int i = 0; i < 4; ++i) {
            const int row = mbase + i * 16 + quad;
            float2 v0 = { acc[i][j][0] + b0, acc[i][j][1] + b1 };
            float2 v1 = { acc[i][j][2] + b0, acc[i][j][3] + b1 };
            *(float2*)(out + (size_t)row * 4096 + col)       = v0;
            *(float2*)(out + (size_t)(row + 8) * 4096 + col) = v1;
        }
    }
}

// ---------------------------------------------------------------------------
// Launch: exactly 3 kernels per call.
// ---------------------------------------------------------------------------
extern "C" void kernel_launch(void* const* d_in, const int* in_sizes, int n_in,
                              void* d_out, int out_size) {
    (void)in_sizes; (void)n_in; (void)out_size;
    const int*   AN   = (const int*)  d_in[0];
    const int*   AS   = (const int*)  d_in[1];
    const int*   AO   = (const int*)  d_in[2];
    const float* SFAN = (const float*)d_in[3];
    const float* SFAS = (const float*)d_in[4];
    const float* SFAO = (const float*)d_in[5];
    const int*   BN   = (const int*)  d_in[6];
    const int*   BS   = (const int*)  d_in[7];
    const int*   BO   = (const int*)  d_in[8];
    const float* SFBN = (const float*)d_in[9];
    const float* SFBS = (const float*)d_in[10];
    const float* SFBO = (const float*)d_in[11];
    const float* bias = (const float*)d_in[12];
    float* out = (float*)d_out;

    __half* Ad;  cudaGetSymbolAddress((void**)&Ad, g_Adeq);
    __half* Bd;  cudaGetSymbolAddress((void**)&Bd, g_Bdeq);

    dequant_fused_kernel<<<8192, 512>>>(AN, SFAN, AS, SFAS, AO, SFAO, Ad);
    dequant_fused_kernel<<<4096, 512>>>(BN, SFBN, BS, SFBS, BO, SFBO, Bd);

    cudaFuncSetAttribute(mixed_gemm_kernel,
                         cudaFuncAttributeMaxDynamicSharedMemorySize, SMEM_SZ);
    // grid: x = N tiles (4096/128 = 32), y = M tiles (8192/256 = 32)
    mixed_gemm_kernel<<<dim3(32, 32), 256, SMEM_SZ>>>(bias, out);
}

// round 8
// speedup vs baseline: 1.3051x; 1.3051x over previous
#include <cuda_runtime.h>
#include <cstdint>
#include <cstddef>

// ---------------------------------------------------------------------------
// QLinearLayer mixed 4/6/8-bit microscaled GEMM, M=8192 N=4096 K=4096, G=32.
// Plain sm_100 -> legacy mma.sync. Legacy fp16 HMMA measured at ~rt16/SMSP
// (950+ us floor), so switch to int8 IMMA m16n8k32: 2x MACs/instr AND exact:
// each k32 instruction spans exactly one scale group; rescale the int32 group
// dot with sa*sb in fp32 (products < 2^24 -> exact convert).
// Pass 1: repack int32 -> int8 scratch + transposed scale tables.
// Pass 2: pipelined IMMA GEMM, CTA 256x128, warp 64x64, K-chunk 128, 3 stages.
// ---------------------------------------------------------------------------

static __device__ int8_t g_A8[(size_t)8192 * 4096];   // 32 MB
static __device__ int8_t g_B8[(size_t)4096 * 4096];   // 16 MB
static __device__ float  g_SAT[(size_t)128 * 8192];   // 4 MB  SAT[g][m]
static __device__ float  g_SBT[(size_t)128 * 4096];   // 2 MB  SBT[g][n]

#define DI static __device__ __forceinline__

DI uint32_t smem_u32(const void* p) {
    uint32_t a;
    asm("{ .reg .u64 t; cvta.to.shared.u64 t, %1; cvt.u32.u64 %0, t; }"
        : "=r"(a) : "l"(p));
    return a;
}
DI void cp_async16(uint32_t smem, const void* gmem) {
    asm volatile("cp.async.cg.shared.global [%0], [%1], 16;"
                 :: "r"(smem), "l"(gmem) : "memory");
}
DI void cp_commit() { asm volatile("cp.async.commit_group;" ::: "memory"); }
template <int N> DI void cp_wait() {
    asm volatile("cp.async.wait_group %0;" :: "n"(N) : "memory");
}
DI void ldsm4(uint32_t* r, uint32_t addr) {
    asm volatile("ldmatrix.sync.aligned.m8n8.x4.shared.b16 {%0,%1,%2,%3}, [%4];"
                 : "=r"(r[0]), "=r"(r[1]), "=r"(r[2]), "=r"(r[3]) : "r"(addr));
}
// int8 MMA, zero C (separate D), one k32 scale group per call.
DI void imma16832(int* d, const uint32_t* a, uint32_t b0, uint32_t b1) {
    asm volatile(
        "mma.sync.aligned.m16n8k32.row.col.s32.s8.s8.s32 "
        "{%0,%1,%2,%3}, {%4,%5,%6,%7}, {%8,%9}, {%10,%11,%12,%13};"
        : "=r"(d[0]), "=r"(d[1]), "=r"(d[2]), "=r"(d[3])
        : "r"(a[0]), "r"(a[1]), "r"(a[2]), "r"(a[3]), "r"(b0), "r"(b1),
          "r"(0), "r"(0), "r"(0), "r"(0));
}

// ---------------------------------------------------------------------------
// Repack: int32 quant values -> int8 (all segments fit int8 range), plus
// transposed scale table sct[g][row].  One block per row, 512 threads.
//   cols: int4 [0,2048) / int6 [2048,3072) / int8 [3072,4096)
//   groups: g<64 -> SF4[m][g]; 64<=g<96 -> SF6[m][g-64]; else SF8[m][g-96]
// ---------------------------------------------------------------------------
__global__ void __launch_bounds__(512)
repack_kernel(const int* __restrict__ Q4, const float* __restrict__ SF4,
              const int* __restrict__ Q6, const float* __restrict__ SF6,
              const int* __restrict__ Q8, const float* __restrict__ SF8,
              int8_t* __restrict__ dst8, float* __restrict__ sct, int nrows) {
    const int m = blockIdx.x;
    const int t = threadIdx.x;
    const int c = t * 8;
    const int* q;
    if (c < 2048)      q = Q4 + (size_t)m * 2048 + c;
    else if (c < 3072) q = Q6 + (size_t)m * 1024 + (c - 2048);
    else               q = Q8 + (size_t)m * 1024 + (c - 3072);
    int4 a = __ldg((const int4*)q);
    int4 b = __ldg((const int4*)q + 1);
    uint32_t lo = (a.x & 255) | ((a.y & 255) << 8) | ((a.z & 255) << 16) |
                  ((uint32_t)(a.w & 255) << 24);
    uint32_t hi = (b.x & 255) | ((b.y & 255) << 8) | ((b.z & 255) << 16) |
                  ((uint32_t)(b.w & 255) << 24);
    *(uint2*)(dst8 + (size_t)m * 4096 + c) = make_uint2(lo, hi);

    if (t < 128) {
        float s;
        if (t < 64)      s = __ldg(&SF4[(size_t)m * 64 + t]);
        else if (t < 96) s = __ldg(&SF6[(size_t)m * 32 + (t - 64)]);
        else             s = __ldg(&SF8[(size_t)m * 32 + (t - 96)]);
        sct[(size_t)t * nrows + m] = s;
    }
}

// ---------------------------------------------------------------------------
// GEMM config: CTA 256(M) x 128(N), 8 warps 4(M) x 2(N) -> warp 64x64.
// K-chunk 128 int8 (= 4 scale groups), 3-stage cp.async pipeline.
// Tiles stored 128B/row with XOR swizzle: chunk16' = chunk16 ^ (row & 7)
// -> conflict-free ldmatrix and full-rate cp.async stores.
// Per stage also stages the 4 groups' scale slices (SA 4KB, SB 2KB).
// ---------------------------------------------------------------------------
static constexpr int      STAGES  = 3;
static constexpr int      NCH     = 32;        // 4096 / 128
static constexpr uint32_t SA_OFF  = 0;         // 256*128 = 32768
static constexpr uint32_t SB_OFF  = 32768;     // 128*128 = 16384
static constexpr uint32_t SSA_OFF = 49152;     // 4*256*4 = 4096
static constexpr uint32_t SSB_OFF = 53248;     // 4*128*4 = 2048
static constexpr uint32_t STG     = 55296;
static constexpr uint32_t SMEM_SZ = STAGES * STG;  // 165888

__global__ void __launch_bounds__(256, 1)
mixed_gemm_kernel(const float* __restrict__ bias, float* __restrict__ out) {
    extern __shared__ __align__(128) char smem[];
    const uint32_t sb = smem_u32(smem);
    const int tid  = threadIdx.x;
    const int lane = tid & 31;
    const int w    = tid >> 5;
    const int wm   = w >> 1;       // 0..3 (M quarters)
    const int wn   = w & 1;        // 0..1 (N halves)
    const int mt   = blockIdx.y;   // 32 M tiles (256 rows)
    const int ntb  = blockIdx.x;   // 32 N tiles (128 rows)

    const char* gA = (const char*)g_A8 + (size_t)mt  * 256 * 4096;
    const char* gB = (const char*)g_B8 + (size_t)ntb * 128 * 4096;

    auto load_stage = [&](int st, int kc) {
        const uint32_t d = sb + st * STG;
        const size_t  gk = (size_t)kc * 128;
        // A: 2048 16B chunks (8/thread)
        #pragma unroll
        for (int u = 0; u < 8; ++u) {
            const int ch = tid + u * 256;
            const int r = ch >> 3, c = ch & 7;
            cp_async16(d + SA_OFF + r * 128 + ((c ^ (r & 7)) << 4),
                       gA + (size_t)r * 4096 + gk + c * 16);
        }
        // B: 1024 chunks (4/thread)
        #pragma unroll
        for (int u = 0; u < 4; ++u) {
            const int ch = tid + u * 256;
            const int r = ch >> 3, c = ch & 7;
            cp_async16(d + SB_OFF + r * 128 + ((c ^ (r & 7)) << 4),
                       gB + (size_t)r * 4096 + gk + c * 16);
        }
        // SA slice: 4 groups x 256 floats (1/thread)
        {
            const int gq = tid >> 6, off = (tid & 63) * 16;
            cp_async16(d + SSA_OFF + gq * 1024 + off,
                       (const char*)g_SAT +
                           ((size_t)(4 * kc + gq) * 8192 + (size_t)mt * 256) * 4 + off);
        }
        // SB slice: 4 groups x 128 floats (threads 0-127)
        if (tid < 128) {
            const int gq = tid >> 5, off = (tid & 31) * 16;
            cp_async16(d + SSB_OFF + gq * 512 + off,
                       (const char*)g_SBT +
                           ((size_t)(4 * kc + gq) * 4096 + (size_t)ntb * 128) * 4 + off);
        }
    };

    // prologue
    #pragma unroll
    for (int st = 0; st < STAGES - 1; ++st) { load_stage(st, st); cp_commit(); }

    float acc[4][8][4];
    #pragma unroll
    for (int i = 0; i < 4; ++i)
        #pragma unroll
        for (int j = 0; j < 8; ++j)
            #pragma unroll
            for (int k = 0; k < 4; ++k) acc[i][j][k] = 0.f;

    // ldmatrix lane mapping: m0=(rows0-7,k16:0) m1=(rows8-15,0) m2=(0-7,1) m3=(8-15,1)
    const int grp   = lane >> 3;
    const int rin16 = (lane & 7) + ((grp & 1) << 3);
    const int khq   = grp >> 1;          // which 16B half within the k32 group
    const int quad  = lane >> 2;         // output row within 8
    const int qt    = lane & 3;          // output col pair

    int s = 0;
    for (int kc = 0; kc < NCH; ++kc) {
        cp_wait<STAGES - 2>();
        __syncthreads();

        const int kl = kc + STAGES - 1;
        if (kl < NCH) load_stage(kl % STAGES, kl);
        cp_commit();

        const uint32_t base = sb + s * STG;

        #pragma unroll 1
        for (int g = 0; g < 4; ++g) {            // 4 scale groups per chunk
            // scales from smem
            float sa[4][2], sbv[8][2];
            #pragma unroll
            for (int i = 0; i < 4; ++i)
                #pragma unroll
                for (int h = 0; h < 2; ++h)
                    asm("ld.shared.f32 %0, [%1];" : "=f"(sa[i][h])
                        : "r"(base + SSA_OFF +
                              (uint32_t)(g * 256 + wm * 64 + i * 16 + h * 8 + quad) * 4));
            #pragma unroll
            for (int j = 0; j < 8; ++j)
                asm("ld.shared.v2.f32 {%0,%1}, [%2];"
                    : "=f"(sbv[j][0]), "=f"(sbv[j][1])
                    : "r"(base + SSB_OFF +
                          (uint32_t)(g * 128 + wn * 64 + j * 8 + qt * 2) * 4));

            const int c16 = g * 2 + khq;
            uint32_t af[4][4], bf[4][4];
            #pragma unroll
            for (int i = 0; i < 4; ++i) {
                const int row = wm * 64 + i * 16 + rin16;
                ldsm4(af[i], base + SA_OFF + row * 128 + ((c16 ^ (row & 7)) << 4));
            }
            #pragma unroll
            for (int j2 = 0; j2 < 4; ++j2) {
                const int row = wn * 64 + j2 * 16 + rin16;
                ldsm4(bf[j2], base + SB_OFF + row * 128 + ((c16 ^ (row & 7)) << 4));
            }
            // bf[j2]: [0]=(n0-7,k0-15) [1]=(n8-15,k0-15) [2]=(n0-7,k16-31) [3]=(n8-15,k16-31)
            #pragma unroll
            for (int i = 0; i < 4; ++i) {
                #pragma unroll
                for (int j2 = 0; j2 < 4; ++j2) {
                    int d0[4], d1[4];
                    imma16832(d0, af[i], bf[j2][0], bf[j2][2]);
                    imma16832(d1, af[i], bf[j2][1], bf[j2][3]);
                    const int j = 2 * j2, jj = j + 1;
                    acc[i][j][0]  = fmaf((float)d0[0] * sa[i][0], sbv[j][0],  acc[i][j][0]);
                    acc[i][j][1]  = fmaf((float)d0[1] * sa[i][0], sbv[j][1],  acc[i][j][1]);
                    acc[i][j][2]  = fmaf((float)d0[2] * sa[i][1], sbv[j][0],  acc[i][j][2]);
                    acc[i][j][3]  = fmaf((float)d0[3] * sa[i][1], sbv[j][1],  acc[i][j][3]);
                    acc[i][jj][0] = fmaf((float)d1[0] * sa[i][0], sbv[jj][0], acc[i][jj][0]);
                    acc[i][jj][1] = fmaf((float)d1[1] * sa[i][0], sbv[jj][1], acc[i][jj][1]);
                    acc[i][jj][2] = fmaf((float)d1[2] * sa[i][1], sbv[jj][0], acc[i][jj][2]);
                    acc[i][jj][3] = fmaf((float)d1[3] * sa[i][1], sbv[jj][1], acc[i][jj][3]);
                }
            }
        }
        if (++s == STAGES) s = 0;
    }

    // ------------------------- epilogue -------------------------
    const int mbase = mt * 256 + wm * 64;
    const int nbase = ntb * 128 + wn * 64;
    #pragma unroll
    for (int j = 0; j < 8; ++j) {
        const int col = nbase + j * 8 + qt * 2;
        const float b0 = __ldg(bias + col);
        const float b1 = __ldg(bias + col + 1);
        #pragma unroll
        for (int i = 0; i < 4; ++i) {
            const int row = mbase + i * 16 + quad;
            float2 v0 = { acc[i][j][0] + b0, acc[i][j][1] + b1 };
            float2 v1 = { acc[i][j][2] + b0, acc[i][j][3] + b1 };
            *(float2*)(out + (size_t)row * 4096 + col)       = v0;
            *(float2*)(out + (size_t)(row + 8) * 4096 + col) = v1;
        }
    }
}

// ---------------------------------------------------------------------------
// Launch: exactly 3 kernels per call.
// ---------------------------------------------------------------------------
extern "C" void kernel_launch(void* const* d_in, const int* in_sizes, int n_in,
                              void* d_out, int out_size) {
    (void)in_sizes; (void)n_in; (void)out_size;
    const int*   AN   = (const int*)  d_in[0];
    const int*   AS   = (const int*)  d_in[1];
    const int*   AO   = (const int*)  d_in[2];
    const float* SFAN = (const float*)d_in[3];
    const float* SFAS = (const float*)d_in[4];
    const float* SFAO = (const float*)d_in[5];
    const int*   BN   = (const int*)  d_in[6];
    const int*   BS   = (const int*)  d_in[7];
    const int*   BO   = (const int*)  d_in[8];
    const float* SFBN = (const float*)d_in[9];
    const float* SFBS = (const float*)d_in[10];
    const float* SFBO = (const float*)d_in[11];
    const float* bias = (const float*)d_in[12];
    float* out = (float*)d_out;

    int8_t* A8;  cudaGetSymbolAddress((void**)&A8,  g_A8);
    int8_t* B8;  cudaGetSymbolAddress((void**)&B8,  g_B8);
    float*  SAT; cudaGetSymbolAddress((void**)&SAT, g_SAT);
    float*  SBT; cudaGetSymbolAddress((void**)&SBT, g_SBT);

    repack_kernel<<<8192, 512>>>(AN, SFAN, AS, SFAS, AO, SFAO, A8, SAT, 8192);
    repack_kernel<<<4096, 512>>>(BN, SFBN, BS, SFBS, BO, SFBO, B8, SBT, 4096);

    cudaFuncSetAttribute(mixed_gemm_kernel,
                         cudaFuncAttributeMaxDynamicSharedMemorySize, (int)SMEM_SZ);
    // grid: x = N tiles (4096/128 = 32), y = M tiles (8192/256 = 32)
    mixed_gemm_kernel<<<dim3(32, 32), 256, SMEM_SZ>>>(bias, out);
}